// round 7
// baseline (speedup 1.0000x reference)
#include <cuda_runtime.h>
#include <cuda_bf16.h>
#include <cstdint>

#define B_SZ 256
#define ED   128
#define HID  256
#define FEAT 2688
#define NENT 40943
#define W2COLS 344064   // FEAT*ED
#define NJC  84         // 84 * 32 = 2688 j-chunks

__device__ float d_E1[B_SZ * ED];
__device__ float d_R[B_SZ * ED];
__device__ float d_stats[2];
__device__ float d_H[4 * B_SZ * HID];      // planes: Hc, Hcb, Hf, Hfb
__device__ float d_filt[B_SZ * 288];
__device__ float d_cbias[B_SZ * 32];
__device__ float d_fcb[B_SZ * ED];
__device__ float d_X[B_SZ * FEAT];
__device__ float d_X2p[NJC * B_SZ * ED];   // split-j partials
__device__ float d_X2[B_SZ * ED];
__device__ float d_Xbn[B_SZ * ED];

__global__ void k_gather(const int* __restrict__ e1, const int* __restrict__ r,
                         const float* __restrict__ ent, const float* __restrict__ rel) {
    int idx = blockIdx.x * 256 + threadIdx.x;
    int i = idx >> 7, c = idx & 127;
    d_E1[idx] = ent[(size_t)e1[i] * ED + c];
    d_R[idx]  = rel[(size_t)r[i]  * ED + c];
}

__global__ void k_bn0() {
    __shared__ float rs[8], rss[8];
    int tid = threadIdx.x;
    float s = 0.f, ss = 0.f;
    for (int idx = tid; idx < B_SZ * ED; idx += 256) {
        float v = d_E1[idx]; s += v; ss += v * v;
    }
    for (int o = 16; o; o >>= 1) {
        s  += __shfl_xor_sync(0xffffffffu, s,  o);
        ss += __shfl_xor_sync(0xffffffffu, ss, o);
    }
    if ((tid & 31) == 0) { rs[tid >> 5] = s; rss[tid >> 5] = ss; }
    __syncthreads();
    if (tid == 0) {
        float S = 0.f, SS = 0.f;
        for (int w = 0; w < 8; ++w) { S += rs[w]; SS += rss[w]; }
        const float inv = 1.0f / (B_SZ * ED);
        float m = S * inv, var = SS * inv - m * m;
        d_stats[0] = m; d_stats[1] = rsqrtf(var + 1e-5f);
    }
}

__device__ __forceinline__ const float* selA(int s) {
    return (s == 0) ? d_R : (d_H + (size_t)(s - 1) * (B_SZ * HID));
}
__device__ __forceinline__ float* selC(int s) {
    switch (s) {
        case 0: return d_H;
        case 1: return d_H + B_SZ * HID;
        case 2: return d_H + 2 * B_SZ * HID;
        case 3: return d_H + 3 * B_SZ * HID;
        case 4: return d_filt;
        case 5: return d_cbias;
        default: return d_fcb;
    }
}

// C[256,N] = (relu?)(A[256,K] @ B[K,N]); A,C selected from globals
__global__ void k_gemm64(int aSel, const float* __restrict__ Bw, int cSel,
                         int K, int N, int doRelu) {
    __shared__ float sA[16 * 64];
    __shared__ float sB[16 * 64];
    const float* A = selA(aSel);
    float* C = selC(cSel);
    const int tid = threadIdx.x;
    const int ty = tid >> 4, tx = tid & 15;
    const int i0 = blockIdx.y * 64, n0 = blockIdx.x * 64;
    float acc[4][4] = {};
    for (int kb = 0; kb < K; kb += 16) {
        #pragma unroll
        for (int t = 0; t < 4; ++t) {
            int idx = tid + t * 256;
            int kk = idx & 15, ii = idx >> 4;
            sA[kk * 64 + ii] = A[(i0 + ii) * K + kb + kk];
            int nn = idx & 63, kk2 = idx >> 6;
            int n = n0 + nn;
            sB[kk2 * 64 + nn] = (n < N) ? Bw[(size_t)(kb + kk2) * N + n] : 0.f;
        }
        __syncthreads();
        #pragma unroll
        for (int kk = 0; kk < 16; ++kk) {
            float a[4], b[4];
            #pragma unroll
            for (int u = 0; u < 4; ++u) a[u] = sA[kk * 64 + ty * 4 + u];
            #pragma unroll
            for (int v = 0; v < 4; ++v) b[v] = sB[kk * 64 + tx * 4 + v];
            #pragma unroll
            for (int u = 0; u < 4; ++u)
                #pragma unroll
                for (int v = 0; v < 4; ++v)
                    acc[u][v] = fmaf(a[u], b[v], acc[u][v]);
        }
        __syncthreads();
    }
    #pragma unroll
    for (int u = 0; u < 4; ++u) {
        int row = i0 + ty * 4 + u;
        #pragma unroll
        for (int v = 0; v < 4; ++v) {
            int col = n0 + tx * 4 + v;
            if (col < N) {
                float val = acc[u][v];
                if (doRelu) val = fmaxf(val, 0.f);
                C[(size_t)row * N + col] = val;
            }
        }
    }
}

// per-sample 3x3 conv (groups=B), bn0 applied on load, + cbias, relu
__global__ void k_conv() {
    __shared__ float sx[128];
    __shared__ float sf[288];
    __shared__ float scb[32];
    const int i = blockIdx.x, tid = threadIdx.x;
    const float mean = d_stats[0], istd = d_stats[1];
    if (tid < 128) sx[tid] = (d_E1[i * 128 + tid] - mean) * istd;
    if (tid < 32)  scb[tid] = d_cbias[i * 32 + tid];
    for (int q = tid; q < 288; q += 256) sf[q] = d_filt[i * 288 + q];
    __syncthreads();
    for (int oi = tid; oi < FEAT; oi += 256) {
        int c = oi / 84, rem = oi - c * 84;
        int y = rem / 14, x = rem - y * 14;
        float a = scb[c];
        #pragma unroll
        for (int ky = 0; ky < 3; ++ky)
            #pragma unroll
            for (int kx = 0; kx < 3; ++kx)
                a = fmaf(sx[(y + ky) * 16 + (x + kx)], sf[c * 9 + ky * 3 + kx], a);
        d_X[i * FEAT + oi] = fmaxf(a, 0.f);
    }
}

// Fused: for each j in chunk, F[i,k]=Hf[i,:]@W2[:,j*128+k]; xacc += X[i,j]*F
__global__ void __launch_bounds__(256, 2) k_bigfused(const float* __restrict__ W2) {
    extern __shared__ float sm[];
    float* sH = sm;                  // [h=256][ii=64]
    float* sW = sm + 16384;          // 2 x (16*128)
    float* sX = sm + 16384 + 4096;   // [jj=32][ii padded 65]
    const int tid = threadIdx.x;
    const int ty = tid >> 4, tx = tid & 15;
    const int i0 = blockIdx.y * 64;
    const int jb = blockIdx.x * 32;
    const float* __restrict__ Hf = d_H + 2 * B_SZ * HID;

    for (int t = 0; t < 16; ++t) {
        int idx = tid + t * 256;
        int ii = idx >> 6, h4 = idx & 63;
        float4 v = *(const float4*)(Hf + (i0 + ii) * 256 + h4 * 4);
        sH[(h4 * 4 + 0) * 64 + ii] = v.x;
        sH[(h4 * 4 + 1) * 64 + ii] = v.y;
        sH[(h4 * 4 + 2) * 64 + ii] = v.z;
        sH[(h4 * 4 + 3) * 64 + ii] = v.w;
    }
    for (int t = 0; t < 8; ++t) {
        int idx = tid + t * 256;
        int ii = idx >> 5, jj = idx & 31;
        sX[jj * 65 + ii] = d_X[(i0 + ii) * FEAT + jb + jj];
    }
    const size_t bbase = (size_t)(tid >> 5) * W2COLS + (size_t)jb * 128 + (size_t)(tid & 31) * 4;
    {
        const float* g = W2 + bbase;
        float4 p0 = *(const float4*)g;
        float4 p1 = *(const float4*)(g + (size_t)8 * W2COLS);
        float* wd = sW + (tid >> 5) * 128 + (tid & 31) * 4;
        *(float4*)wd = p0;
        *(float4*)(wd + 1024) = p1;
    }
    __syncthreads();

    float xacc[4][8] = {};
    for (int jj = 0; jj < 32; ++jj) {
        float facc[4][8] = {};
        for (int hs = 0; hs < 16; ++hs) {
            const int s = jj * 16 + hs;
            float4 p0, p1;
            const bool pf = (s < 511);
            if (pf) {
                int s1 = s + 1;
                int jj2 = s1 >> 4, hs2 = s1 & 15;
                const float* g = W2 + bbase + (size_t)hs2 * (16 * (size_t)W2COLS)
                                           + (size_t)jj2 * 128;
                p0 = *(const float4*)g;
                p1 = *(const float4*)(g + (size_t)8 * W2COLS);
            }
            const float* wt  = sW + (s & 1) * 2048 + tx * 4;
            const float* sHa = sH + hs * 1024 + ty * 4;
            #pragma unroll
            for (int hh = 0; hh < 16; ++hh) {
                float4 a4 = *(const float4*)(sHa + hh * 64);
                float4 b0 = *(const float4*)(wt + hh * 128);
                float4 b1 = *(const float4*)(wt + hh * 128 + 64);
                float av[4] = {a4.x, a4.y, a4.z, a4.w};
                float bv[8] = {b0.x, b0.y, b0.z, b0.w, b1.x, b1.y, b1.z, b1.w};
                #pragma unroll
                for (int u = 0; u < 4; ++u)
                    #pragma unroll
                    for (int v = 0; v < 8; ++v)
                        facc[u][v] = fmaf(av[u], bv[v], facc[u][v]);
            }
            if (pf) {
                float* wd = sW + ((s + 1) & 1) * 2048 + (tid >> 5) * 128 + (tid & 31) * 4;
                *(float4*)wd = p0;
                *(float4*)(wd + 1024) = p1;
            }
            __syncthreads();
        }
        #pragma unroll
        for (int u = 0; u < 4; ++u) {
            float xv = sX[jj * 65 + ty * 4 + u];
            #pragma unroll
            for (int v = 0; v < 8; ++v)
                xacc[u][v] = fmaf(xv, facc[u][v], xacc[u][v]);
        }
    }
    float* outp = d_X2p + (size_t)blockIdx.x * (B_SZ * ED) + (size_t)i0 * 128;
    #pragma unroll
    for (int u = 0; u < 4; ++u) {
        int row = ty * 4 + u;
        *(float4*)&outp[row * 128 + tx * 4] =
            make_float4(xacc[u][0], xacc[u][1], xacc[u][2], xacc[u][3]);
        *(float4*)&outp[row * 128 + 64 + tx * 4] =
            make_float4(xacc[u][4], xacc[u][5], xacc[u][6], xacc[u][7]);
    }
}

__global__ void k_reduce() {
    int idx = blockIdx.x * 256 + threadIdx.x;
    float a = d_fcb[idx];
    #pragma unroll 4
    for (int p = 0; p < NJC; ++p) a += d_X2p[p * (B_SZ * ED) + idx];
    d_X2[idx] = a;
}

__global__ void k_bn2() {
    int k = threadIdx.x;   // 128 threads
    float s = 0.f, ss = 0.f;
    for (int i = 0; i < B_SZ; ++i) {
        float v = d_X2[i * 128 + k]; s += v; ss += v * v;
    }
    const float inv = 1.0f / B_SZ;
    float m = s * inv, var = ss * inv - m * m;
    float istd = rsqrtf(var + 1e-5f);
    for (int i = 0; i < B_SZ; ++i) {
        float v = (d_X2[i * 128 + k] - m) * istd;
        d_Xbn[i * 128 + k] = fmaxf(v, 0.f);
    }
}

__global__ void __launch_bounds__(256) k_final(const float* __restrict__ E2,
                                               const float* __restrict__ bias,
                                               float* __restrict__ out) {
    extern __shared__ float sm[];
    float* sA = sm;                 // [128][132]
    float* sB = sm + 128 * 132;     // [64][132]
    const int tid = threadIdx.x;
    const int ty = tid >> 4, tx = tid & 15;
    const int i0 = blockIdx.y * 128;
    const int n0 = blockIdx.x * 64;
    for (int t = 0; t < 64; ++t) {
        int idx = tid + t * 256;
        int ii = idx >> 7, k = idx & 127;
        sA[ii * 132 + k] = d_Xbn[(i0 + ii) * 128 + k];
    }
    for (int t = 0; t < 32; ++t) {
        int idx = tid + t * 256;
        int nn = idx >> 7, k = idx & 127;
        int n = n0 + nn;
        sB[nn * 132 + k] = (n < NENT) ? E2[(size_t)n * 128 + k] : 0.f;
    }
    __syncthreads();
    float acc[8][4] = {};
    for (int k4 = 0; k4 < 128; k4 += 4) {
        float4 bv[4];
        #pragma unroll
        for (int v = 0; v < 4; ++v)
            bv[v] = *(const float4*)&sB[(tx * 4 + v) * 132 + k4];
        #pragma unroll
        for (int u = 0; u < 8; ++u) {
            float4 a = *(const float4*)&sA[(ty * 8 + u) * 132 + k4];
            #pragma unroll
            for (int v = 0; v < 4; ++v) {
                acc[u][v] = fmaf(a.x, bv[v].x, acc[u][v]);
                acc[u][v] = fmaf(a.y, bv[v].y, acc[u][v]);
                acc[u][v] = fmaf(a.z, bv[v].z, acc[u][v]);
                acc[u][v] = fmaf(a.w, bv[v].w, acc[u][v]);
            }
        }
    }
    #pragma unroll
    for (int v = 0; v < 4; ++v) {
        int n = n0 + tx * 4 + v;
        if (n >= NENT) continue;
        float bb = bias[n];
        #pragma unroll
        for (int u = 0; u < 8; ++u) {
            int i = i0 + ty * 8 + u;
            float logit = acc[u][v] + bb;
            out[(size_t)i * NENT + n] = 1.f / (1.f + __expf(-logit));
        }
    }
}

extern "C" void kernel_launch(void* const* d_in, const int* in_sizes, int n_in,
                              void* d_out, int out_size) {
    const int*   e1       = (const int*)d_in[0];
    const int*   r        = (const int*)d_in[1];
    const float* ent      = (const float*)d_in[2];
    const float* rel      = (const float*)d_in[3];
    const float* convw_w1 = (const float*)d_in[4];
    const float* convw_w2 = (const float*)d_in[5];
    const float* convb_w1 = (const float*)d_in[6];
    const float* convb_w2 = (const float*)d_in[7];
    const float* fcw_w1   = (const float*)d_in[8];
    const float* fcw_w2   = (const float*)d_in[9];
    const float* fcb_w1   = (const float*)d_in[10];
    const float* fcb_w2   = (const float*)d_in[11];
    const float* bias     = (const float*)d_in[12];
    float* out = (float*)d_out;

    cudaFuncSetAttribute(k_bigfused, cudaFuncAttributeMaxDynamicSharedMemorySize, 90240);
    cudaFuncSetAttribute(k_final, cudaFuncAttributeMaxDynamicSharedMemorySize, 101376);

    k_gather<<<128, 256>>>(e1, r, ent, rel);
    k_bn0<<<1, 256>>>();
    k_gemm64<<<dim3(4, 4), 256>>>(0, convw_w1, 0, 128, 256, 1);  // Hc
    k_gemm64<<<dim3(4, 4), 256>>>(0, convb_w1, 1, 128, 256, 1);  // Hcb
    k_gemm64<<<dim3(4, 4), 256>>>(0, fcw_w1,   2, 128, 256, 1);  // Hf
    k_gemm64<<<dim3(4, 4), 256>>>(0, fcb_w1,   3, 128, 256, 1);  // Hfb
    k_gemm64<<<dim3(5, 4), 256>>>(1, convw_w2, 4, 256, 288, 0);  // filt
    k_gemm64<<<dim3(1, 4), 256>>>(2, convb_w2, 5, 256, 32, 0);   // cbias
    k_gemm64<<<dim3(2, 4), 256>>>(4, fcb_w2,   6, 256, 128, 0);  // fcb
    k_conv<<<256, 256>>>();
    k_bigfused<<<dim3(NJC, 4), 256, 90240>>>(fcw_w2);
    k_reduce<<<128, 256>>>();
    k_bn2<<<1, 128>>>();
    k_final<<<dim3(640, 2), 256, 101376>>>(ent, bias, out);
}

// round 8
// speedup vs baseline: 1.6011x; 1.6011x over previous
#include <cuda_runtime.h>
#include <cuda_bf16.h>
#include <cstdint>

#define B_SZ 256
#define ED   128
#define HID  256
#define FEAT 2688
#define NENT 40943
#define W2COLS 344064   // FEAT*ED
#define NJC  84         // 84 * 32 = 2688 j-chunks

__device__ float d_E1[B_SZ * ED];
__device__ float d_R[B_SZ * ED];
__device__ float d_stats[2];
__device__ float d_H[4 * B_SZ * HID];      // planes: Hc, Hcb, Hf, Hfb
__device__ float d_filt[B_SZ * 288];
__device__ float d_cbias[B_SZ * 32];
__device__ float d_fcb[B_SZ * ED];
__device__ float d_X[B_SZ * FEAT];
__device__ float d_X2p[NJC * B_SZ * ED];   // split-j partials
__device__ float d_X2[B_SZ * ED];
__device__ float d_Xbn[B_SZ * ED];

__device__ __forceinline__ float tf32r(float x) {
    unsigned u; asm("cvt.rna.tf32.f32 %0, %1;" : "=r"(u) : "f"(x));
    return __uint_as_float(u);
}

__global__ void k_gather(const int* __restrict__ e1, const int* __restrict__ r,
                         const float* __restrict__ ent, const float* __restrict__ rel) {
    int idx = blockIdx.x * 256 + threadIdx.x;
    int i = idx >> 7, c = idx & 127;
    d_E1[idx] = ent[(size_t)e1[i] * ED + c];
    d_R[idx]  = rel[(size_t)r[i]  * ED + c];
}

__global__ void k_bn0() {
    __shared__ float rs[8], rss[8];
    int tid = threadIdx.x;
    float s = 0.f, ss = 0.f;
    for (int idx = tid; idx < B_SZ * ED; idx += 256) {
        float v = d_E1[idx]; s += v; ss += v * v;
    }
    for (int o = 16; o; o >>= 1) {
        s  += __shfl_xor_sync(0xffffffffu, s,  o);
        ss += __shfl_xor_sync(0xffffffffu, ss, o);
    }
    if ((tid & 31) == 0) { rs[tid >> 5] = s; rss[tid >> 5] = ss; }
    __syncthreads();
    if (tid == 0) {
        float S = 0.f, SS = 0.f;
        for (int w = 0; w < 8; ++w) { S += rs[w]; SS += rss[w]; }
        const float inv = 1.0f / (B_SZ * ED);
        float m = S * inv, var = SS * inv - m * m;
        d_stats[0] = m; d_stats[1] = rsqrtf(var + 1e-5f);
    }
}

// shared GEMM body: C[256,N] = (relu?)(A[256,K] @ B[K,N]) for a 64x64 tile
__device__ __forceinline__ void gemm64_body(const float* __restrict__ A,
                                            const float* __restrict__ Bw,
                                            float* __restrict__ C,
                                            int K, int N, int doRelu,
                                            int i0, int n0) {
    __shared__ float sA[16 * 64];
    __shared__ float sB[16 * 64];
    const int tid = threadIdx.x;
    const int ty = tid >> 4, tx = tid & 15;
    float acc[4][4] = {};
    for (int kb = 0; kb < K; kb += 16) {
        #pragma unroll
        for (int t = 0; t < 4; ++t) {
            int idx = tid + t * 256;
            int kk = idx & 15, ii = idx >> 4;
            sA[kk * 64 + ii] = A[(i0 + ii) * K + kb + kk];
            int nn = idx & 63, kk2 = idx >> 6;
            int n = n0 + nn;
            sB[kk2 * 64 + nn] = (n < N) ? Bw[(size_t)(kb + kk2) * N + n] : 0.f;
        }
        __syncthreads();
        #pragma unroll
        for (int kk = 0; kk < 16; ++kk) {
            float a[4], b[4];
            #pragma unroll
            for (int u = 0; u < 4; ++u) a[u] = sA[kk * 64 + ty * 4 + u];
            #pragma unroll
            for (int v = 0; v < 4; ++v) b[v] = sB[kk * 64 + tx * 4 + v];
            #pragma unroll
            for (int u = 0; u < 4; ++u)
                #pragma unroll
                for (int v = 0; v < 4; ++v)
                    acc[u][v] = fmaf(a[u], b[v], acc[u][v]);
        }
        __syncthreads();
    }
    #pragma unroll
    for (int u = 0; u < 4; ++u) {
        int row = i0 + ty * 4 + u;
        #pragma unroll
        for (int v = 0; v < 4; ++v) {
            int col = n0 + tx * 4 + v;
            if (col < N) {
                float val = acc[u][v];
                if (doRelu) val = fmaxf(val, 0.f);
                C[(size_t)row * N + col] = val;
            }
        }
    }
}

// layer-1 CPG: 4 GEMMs [256,128]@[128,256]+relu in one launch (z selects)
__global__ void k_cpg1(const float* __restrict__ w0, const float* __restrict__ w1,
                       const float* __restrict__ w2, const float* __restrict__ w3) {
    const float* Bw = (blockIdx.z == 0) ? w0 : (blockIdx.z == 1) ? w1
                    : (blockIdx.z == 2) ? w2 : w3;
    float* C = d_H + (size_t)blockIdx.z * (B_SZ * HID);
    gemm64_body(d_R, Bw, C, 128, 256, 1, blockIdx.y * 64, blockIdx.x * 64);
}

// layer-2 CPG: filt/cbias/fcb in one launch (z selects)
__global__ void k_cpg2(const float* __restrict__ convw_w2,
                       const float* __restrict__ convb_w2,
                       const float* __restrict__ fcb_w2) {
    int z = blockIdx.z;
    const float* A;
    const float* Bw;
    float* C;
    int N;
    if (z == 0)      { A = d_H;                    Bw = convw_w2; C = d_filt;  N = 288; }
    else if (z == 1) { A = d_H + B_SZ * HID;       Bw = convb_w2; C = d_cbias; N = 32;  }
    else             { A = d_H + 3 * B_SZ * HID;   Bw = fcb_w2;   C = d_fcb;   N = 128; }
    int n0 = blockIdx.x * 64;
    if (n0 >= N) return;
    gemm64_body(A, Bw, C, 256, N, 0, blockIdx.y * 64, n0);
}

// per-sample 3x3 conv (groups=B), bn0 applied on load, + cbias, relu
__global__ void k_conv() {
    __shared__ float sx[128];
    __shared__ float sf[288];
    __shared__ float scb[32];
    const int i = blockIdx.x, tid = threadIdx.x;
    const float mean = d_stats[0], istd = d_stats[1];
    if (tid < 128) sx[tid] = (d_E1[i * 128 + tid] - mean) * istd;
    if (tid < 32)  scb[tid] = d_cbias[i * 32 + tid];
    for (int q = tid; q < 288; q += 256) sf[q] = d_filt[i * 288 + q];
    __syncthreads();
    for (int oi = tid; oi < FEAT; oi += 256) {
        int c = oi / 84, rem = oi - c * 84;
        int y = rem / 14, x = rem - y * 14;
        float a = scb[c];
        #pragma unroll
        for (int ky = 0; ky < 3; ++ky)
            #pragma unroll
            for (int kx = 0; kx < 3; ++kx)
                a = fmaf(sx[(y + ky) * 16 + (x + kx)], sf[c * 9 + ky * 3 + kx], a);
        d_X[i * FEAT + oi] = fmaxf(a, 0.f);
    }
}

// ---------------- dominant contraction on tensor cores (tf32 mma.sync) -----------
// Block: 64 i-rows x 128 k-cols x 32 j's. For each j:
//   F[i,k] = Hf[i,:] @ W2[:, j*128+k]   (tf32 MMA, fp32 accum)
//   xacc[i,k] += X[i,j] * F[i,k]        (fp32)
__global__ void __launch_bounds__(256, 2) k_bigfused(const float* __restrict__ W2) {
    extern __shared__ float sm[];
    float* sA = sm;                       // [h=256][i=64] stride 72 (tf32 bits)
    float* sB = sm + 18432;               // 2 x [16 h][128 k] stride 136 (tf32 bits)
    float* sX = sm + 18432 + 4352;        // [jj=32][i=64] stride 72 (fp32)
    const int tid = threadIdx.x;
    const int lane = tid & 31, wid = tid >> 5;
    const int g = lane >> 2, c = lane & 3;
    const int iw0 = (wid & 3) * 16;       // warp i-offset
    const int kw0 = (wid >> 2) * 64;      // warp k-offset
    const int i0 = blockIdx.x * 64;
    const int jb = blockIdx.y * 32;
    const float* __restrict__ Hf = d_H + 2 * B_SZ * HID;

    // A (Hf) -> smem transposed [h][i], tf32-rounded
    #pragma unroll 4
    for (int t = 0; t < 64; ++t) {
        int idx = tid + t * 256;
        int ii = idx >> 8, h = idx & 255;
        sA[h * 72 + ii] = tf32r(Hf[(i0 + ii) * 256 + h]);
    }
    // X -> smem [jj][i] (fp32)
    #pragma unroll
    for (int t = 0; t < 8; ++t) {
        int idx = tid + t * 256;
        int jj = idx & 31, ii = idx >> 5;
        sX[jj * 72 + ii] = d_X[(i0 + ii) * FEAT + jb + jj];
    }

    // B stage loader mapping: thread -> rows (r, r+8), 4 cols at c4
    const int r = tid >> 5;
    const int c4 = (tid & 31) * 4;

    // prefetch stage 0 (jj=0, hs=0) into buffer 0
    {
        const float* gp = W2 + (size_t)r * W2COLS + (size_t)jb * 128 + c4;
        float4 p0 = *(const float4*)gp;
        float4 p1 = *(const float4*)(gp + (size_t)8 * W2COLS);
        float* dst = sB + r * 136 + c4;
        dst[0] = tf32r(p0.x); dst[1] = tf32r(p0.y);
        dst[2] = tf32r(p0.z); dst[3] = tf32r(p0.w);
        float* dst2 = dst + 8 * 136;
        dst2[0] = tf32r(p1.x); dst2[1] = tf32r(p1.y);
        dst2[2] = tf32r(p1.z); dst2[3] = tf32r(p1.w);
    }
    __syncthreads();

    float xacc[8][4] = {};
    float facc[8][4] = {};
    for (int s = 0; s < 512; ++s) {            // 32 j * 16 h-stages
        const int buf = s & 1;
        float4 p0, p1;
        const bool pf = (s + 1 < 512);
        if (pf) {
            int s1 = s + 1;
            int jj2 = s1 >> 4, hs2 = s1 & 15;
            const float* gp = W2 + (size_t)(hs2 * 16 + r) * W2COLS
                                 + (size_t)(jb + jj2) * 128 + c4;
            p0 = *(const float4*)gp;
            p1 = *(const float4*)(gp + (size_t)8 * W2COLS);
        }
        const int hg = (s & 15) * 16;          // global h base of this stage
        const float* bbuf = sB + buf * 2176;
        #pragma unroll
        for (int ks = 0; ks < 2; ++ks) {
            const int hb = hg + ks * 8;
            unsigned a0 = __float_as_uint(sA[(hb + c) * 72 + iw0 + g]);
            unsigned a1 = __float_as_uint(sA[(hb + c) * 72 + iw0 + g + 8]);
            unsigned a2 = __float_as_uint(sA[(hb + c + 4) * 72 + iw0 + g]);
            unsigned a3 = __float_as_uint(sA[(hb + c + 4) * 72 + iw0 + g + 8]);
            #pragma unroll
            for (int t = 0; t < 8; ++t) {
                unsigned b0 = __float_as_uint(bbuf[(ks * 8 + c) * 136 + kw0 + t * 8 + g]);
                unsigned b1 = __float_as_uint(bbuf[(ks * 8 + c + 4) * 136 + kw0 + t * 8 + g]);
                asm volatile(
                    "mma.sync.aligned.m16n8k8.row.col.f32.tf32.tf32.f32 "
                    "{%0,%1,%2,%3},{%4,%5,%6,%7},{%8,%9},{%0,%1,%2,%3};"
                    : "+f"(facc[t][0]), "+f"(facc[t][1]),
                      "+f"(facc[t][2]), "+f"(facc[t][3])
                    : "r"(a0), "r"(a1), "r"(a2), "r"(a3), "r"(b0), "r"(b1));
            }
        }
        if (pf) {
            float* dst = sB + (buf ^ 1) * 2176 + r * 136 + c4;
            dst[0] = tf32r(p0.x); dst[1] = tf32r(p0.y);
            dst[2] = tf32r(p0.z); dst[3] = tf32r(p0.w);
            float* dst2 = dst + 8 * 136;
            dst2[0] = tf32r(p1.x); dst2[1] = tf32r(p1.y);
            dst2[2] = tf32r(p1.z); dst2[3] = tf32r(p1.w);
        }
        if ((s & 15) == 15) {                  // end of one j: contract with X
            int jj = s >> 4;
            float xv0 = sX[jj * 72 + iw0 + g];
            float xv1 = sX[jj * 72 + iw0 + g + 8];
            #pragma unroll
            for (int t = 0; t < 8; ++t) {
                xacc[t][0] = fmaf(xv0, facc[t][0], xacc[t][0]);
                xacc[t][1] = fmaf(xv0, facc[t][1], xacc[t][1]);
                xacc[t][2] = fmaf(xv1, facc[t][2], xacc[t][2]);
                xacc[t][3] = fmaf(xv1, facc[t][3], xacc[t][3]);
                facc[t][0] = 0.f; facc[t][1] = 0.f;
                facc[t][2] = 0.f; facc[t][3] = 0.f;
            }
        }
        __syncthreads();
    }

    // write partial plane (rows g/g+8, cols 2c/2c+1 per mma layout)
    float* outp = d_X2p + (size_t)blockIdx.y * (B_SZ * ED) + (size_t)i0 * 128;
    #pragma unroll
    for (int t = 0; t < 8; ++t) {
        int col = kw0 + t * 8 + 2 * c;
        int row0 = iw0 + g, row1 = iw0 + g + 8;
        *(float2*)&outp[row0 * 128 + col] = make_float2(xacc[t][0], xacc[t][1]);
        *(float2*)&outp[row1 * 128 + col] = make_float2(xacc[t][2], xacc[t][3]);
    }
}

__global__ void k_reduce() {
    int idx = blockIdx.x * 256 + threadIdx.x;
    float a = d_fcb[idx];
    #pragma unroll 4
    for (int p = 0; p < NJC; ++p) a += d_X2p[p * (B_SZ * ED) + idx];
    d_X2[idx] = a;
}

__global__ void k_bn2() {
    int k = threadIdx.x;   // 128 threads
    float s = 0.f, ss = 0.f;
    for (int i = 0; i < B_SZ; ++i) {
        float v = d_X2[i * 128 + k]; s += v; ss += v * v;
    }
    const float inv = 1.0f / B_SZ;
    float m = s * inv, var = ss * inv - m * m;
    float istd = rsqrtf(var + 1e-5f);
    for (int i = 0; i < B_SZ; ++i) {
        float v = (d_X2[i * 128 + k] - m) * istd;
        d_Xbn[i * 128 + k] = fmaxf(v, 0.f);
    }
}

__global__ void __launch_bounds__(256) k_final(const float* __restrict__ E2,
                                               const float* __restrict__ bias,
                                               float* __restrict__ out) {
    extern __shared__ float sm[];
    float* sA = sm;                 // [128][132]
    float* sB = sm + 128 * 132;     // [64][132]
    const int tid = threadIdx.x;
    const int ty = tid >> 4, tx = tid & 15;
    const int i0 = blockIdx.y * 128;
    const int n0 = blockIdx.x * 64;
    for (int t = 0; t < 64; ++t) {
        int idx = tid + t * 256;
        int ii = idx >> 7, k = idx & 127;
        sA[ii * 132 + k] = d_Xbn[(i0 + ii) * 128 + k];
    }
    for (int t = 0; t < 32; ++t) {
        int idx = tid + t * 256;
        int nn = idx >> 7, k = idx & 127;
        int n = n0 + nn;
        sB[nn * 132 + k] = (n < NENT) ? E2[(size_t)n * 128 + k] : 0.f;
    }
    __syncthreads();
    float acc[8][4] = {};
    for (int k4 = 0; k4 < 128; k4 += 4) {
        float4 bv[4];
        #pragma unroll
        for (int v = 0; v < 4; ++v)
            bv[v] = *(const float4*)&sB[(tx * 4 + v) * 132 + k4];
        #pragma unroll
        for (int u = 0; u < 8; ++u) {
            float4 a = *(const float4*)&sA[(ty * 8 + u) * 132 + k4];
            #pragma unroll
            for (int v = 0; v < 4; ++v) {
                acc[u][v] = fmaf(a.x, bv[v].x, acc[u][v]);
                acc[u][v] = fmaf(a.y, bv[v].y, acc[u][v]);
                acc[u][v] = fmaf(a.z, bv[v].z, acc[u][v]);
                acc[u][v] = fmaf(a.w, bv[v].w, acc[u][v]);
            }
        }
    }
    #pragma unroll
    for (int v = 0; v < 4; ++v) {
        int n = n0 + tx * 4 + v;
        if (n >= NENT) continue;
        float bb = bias[n];
        #pragma unroll
        for (int u = 0; u < 8; ++u) {
            int i = i0 + ty * 8 + u;
            float logit = acc[u][v] + bb;
            out[(size_t)i * NENT + n] = 1.f / (1.f + __expf(-logit));
        }
    }
}

extern "C" void kernel_launch(void* const* d_in, const int* in_sizes, int n_in,
                              void* d_out, int out_size) {
    const int*   e1       = (const int*)d_in[0];
    const int*   r        = (const int*)d_in[1];
    const float* ent      = (const float*)d_in[2];
    const float* rel      = (const float*)d_in[3];
    const float* convw_w1 = (const float*)d_in[4];
    const float* convw_w2 = (const float*)d_in[5];
    const float* convb_w1 = (const float*)d_in[6];
    const float* convb_w2 = (const float*)d_in[7];
    const float* fcw_w1   = (const float*)d_in[8];
    const float* fcw_w2   = (const float*)d_in[9];
    const float* fcb_w1   = (const float*)d_in[10];
    const float* fcb_w2   = (const float*)d_in[11];
    const float* bias     = (const float*)d_in[12];
    float* out = (float*)d_out;

    cudaFuncSetAttribute(k_bigfused, cudaFuncAttributeMaxDynamicSharedMemorySize, 100352);
    cudaFuncSetAttribute(k_final, cudaFuncAttributeMaxDynamicSharedMemorySize, 101376);

    k_gather<<<128, 256>>>(e1, r, ent, rel);
    k_bn0<<<1, 256>>>();
    k_cpg1<<<dim3(4, 4, 4), 256>>>(convw_w1, convb_w1, fcw_w1, fcb_w1);
    k_cpg2<<<dim3(5, 4, 3), 256>>>(convw_w2, convb_w2, fcb_w2);
    k_conv<<<256, 256>>>();
    k_bigfused<<<dim3(4, NJC), 256, 100352>>>(fcw_w2);
    k_reduce<<<128, 256>>>();
    k_bn2<<<1, 128>>>();
    k_final<<<dim3(640, 2), 256, 101376>>>(ent, bias, out);
}

// round 9
// speedup vs baseline: 2.5292x; 1.5797x over previous
#include <cuda_runtime.h>
#include <cuda_bf16.h>
#include <cstdint>

#define B_SZ 256
#define ED   128
#define HID  256
#define FEAT 2688
#define NENT 40943
#define W2COLS 344064   // FEAT*ED
#define NJC  84         // 84 * 32 = 2688 j-chunks

__device__ float d_E1[B_SZ * ED];
__device__ float d_R[B_SZ * ED];
__device__ float d_stats[2];
__device__ float d_H[4 * B_SZ * HID];      // planes: Hc, Hcb, Hf, Hfb
__device__ float d_filt[B_SZ * 288];
__device__ float d_cbias[B_SZ * 32];
__device__ float d_fcb[B_SZ * ED];
__device__ float d_X[B_SZ * FEAT];
__device__ float d_X2p[NJC * B_SZ * ED];   // split-j partials
__device__ float d_X2[B_SZ * ED];
__device__ float d_Xbn[B_SZ * ED];

__device__ __forceinline__ uint32_t pack_bf2(float lo, float hi) {
    __nv_bfloat162 b = __floats2bfloat162_rn(lo, hi);   // x=lo(low16), y=hi
    return *reinterpret_cast<uint32_t*>(&b);
}

__global__ void k_gather(const int* __restrict__ e1, const int* __restrict__ r,
                         const float* __restrict__ ent, const float* __restrict__ rel) {
    int idx = blockIdx.x * 256 + threadIdx.x;
    int i = idx >> 7, c = idx & 127;
    d_E1[idx] = ent[(size_t)e1[i] * ED + c];
    d_R[idx]  = rel[(size_t)r[i]  * ED + c];
}

__global__ void k_bn0() {
    __shared__ float rs[8], rss[8];
    int tid = threadIdx.x;
    float s = 0.f, ss = 0.f;
    for (int idx = tid; idx < B_SZ * ED; idx += 256) {
        float v = d_E1[idx]; s += v; ss += v * v;
    }
    for (int o = 16; o; o >>= 1) {
        s  += __shfl_xor_sync(0xffffffffu, s,  o);
        ss += __shfl_xor_sync(0xffffffffu, ss, o);
    }
    if ((tid & 31) == 0) { rs[tid >> 5] = s; rss[tid >> 5] = ss; }
    __syncthreads();
    if (tid == 0) {
        float S = 0.f, SS = 0.f;
        for (int w = 0; w < 8; ++w) { S += rs[w]; SS += rss[w]; }
        const float inv = 1.0f / (B_SZ * ED);
        float m = S * inv, var = SS * inv - m * m;
        d_stats[0] = m; d_stats[1] = rsqrtf(var + 1e-5f);
    }
}

// shared GEMM body: C[256,N] = (relu?)(A[256,K] @ B[K,N]) for a 64x64 tile
__device__ __forceinline__ void gemm64_body(const float* __restrict__ A,
                                            const float* __restrict__ Bw,
                                            float* __restrict__ C,
                                            int K, int N, int doRelu,
                                            int i0, int n0) {
    __shared__ float sA[16 * 64];
    __shared__ float sB[16 * 64];
    const int tid = threadIdx.x;
    const int ty = tid >> 4, tx = tid & 15;
    float acc[4][4] = {};
    for (int kb = 0; kb < K; kb += 16) {
        #pragma unroll
        for (int t = 0; t < 4; ++t) {
            int idx = tid + t * 256;
            int kk = idx & 15, ii = idx >> 4;
            sA[kk * 64 + ii] = A[(i0 + ii) * K + kb + kk];
            int nn = idx & 63, kk2 = idx >> 6;
            int n = n0 + nn;
            sB[kk2 * 64 + nn] = (n < N) ? Bw[(size_t)(kb + kk2) * N + n] : 0.f;
        }
        __syncthreads();
        #pragma unroll
        for (int kk = 0; kk < 16; ++kk) {
            float a[4], b[4];
            #pragma unroll
            for (int u = 0; u < 4; ++u) a[u] = sA[kk * 64 + ty * 4 + u];
            #pragma unroll
            for (int v = 0; v < 4; ++v) b[v] = sB[kk * 64 + tx * 4 + v];
            #pragma unroll
            for (int u = 0; u < 4; ++u)
                #pragma unroll
                for (int v = 0; v < 4; ++v)
                    acc[u][v] = fmaf(a[u], b[v], acc[u][v]);
        }
        __syncthreads();
    }
    #pragma unroll
    for (int u = 0; u < 4; ++u) {
        int row = i0 + ty * 4 + u;
        #pragma unroll
        for (int v = 0; v < 4; ++v) {
            int col = n0 + tx * 4 + v;
            if (col < N) {
                float val = acc[u][v];
                if (doRelu) val = fmaxf(val, 0.f);
                C[(size_t)row * N + col] = val;
            }
        }
    }
}

__global__ void k_cpg1(const float* __restrict__ w0, const float* __restrict__ w1,
                       const float* __restrict__ w2, const float* __restrict__ w3) {
    const float* Bw = (blockIdx.z == 0) ? w0 : (blockIdx.z == 1) ? w1
                    : (blockIdx.z == 2) ? w2 : w3;
    float* C = d_H + (size_t)blockIdx.z * (B_SZ * HID);
    gemm64_body(d_R, Bw, C, 128, 256, 1, blockIdx.y * 64, blockIdx.x * 64);
}

__global__ void k_cpg2(const float* __restrict__ convw_w2,
                       const float* __restrict__ convb_w2,
                       const float* __restrict__ fcb_w2) {
    int z = blockIdx.z;
    const float* A;
    const float* Bw;
    float* C;
    int N;
    if (z == 0)      { A = d_H;                  Bw = convw_w2; C = d_filt;  N = 288; }
    else if (z == 1) { A = d_H + B_SZ * HID;     Bw = convb_w2; C = d_cbias; N = 32;  }
    else             { A = d_H + 3 * B_SZ * HID; Bw = fcb_w2;   C = d_fcb;   N = 128; }
    int n0 = blockIdx.x * 64;
    if (n0 >= N) return;
    gemm64_body(A, Bw, C, 256, N, 0, blockIdx.y * 64, n0);
}

__global__ void k_conv() {
    __shared__ float sx[128];
    __shared__ float sf[288];
    __shared__ float scb[32];
    const int i = blockIdx.x, tid = threadIdx.x;
    const float mean = d_stats[0], istd = d_stats[1];
    if (tid < 128) sx[tid] = (d_E1[i * 128 + tid] - mean) * istd;
    if (tid < 32)  scb[tid] = d_cbias[i * 32 + tid];
    for (int q = tid; q < 288; q += 256) sf[q] = d_filt[i * 288 + q];
    __syncthreads();
    for (int oi = tid; oi < FEAT; oi += 256) {
        int c = oi / 84, rem = oi - c * 84;
        int y = rem / 14, x = rem - y * 14;
        float a = scb[c];
        #pragma unroll
        for (int ky = 0; ky < 3; ++ky)
            #pragma unroll
            for (int kx = 0; kx < 3; ++kx)
                a = fmaf(sx[(y + ky) * 16 + (x + kx)], sf[c * 9 + ky * 3 + kx], a);
        d_X[i * FEAT + oi] = fmaxf(a, 0.f);
    }
}

// ---------- dominant contraction: bf16 mma.sync m16n8k16, fp32 accum ----------
// Block: 64 i-rows x 128 k-cols x 32 j's.  Stage = 32 h (2 k16 steps), 256 stages.
// smem words: sApk [k2=128][72], sB 2x[k2=16][136], sX [32][72] fp32.
__global__ void __launch_bounds__(256, 2) k_bigfused(const float* __restrict__ W2) {
    extern __shared__ uint32_t smw[];
    uint32_t* sApk = smw;                   // 9216
    uint32_t* sBpk = smw + 9216;            // 4352 (2 buffers of 2176)
    float*    sX   = (float*)(smw + 13568); // 2304
    const int tid = threadIdx.x;
    const int lane = tid & 31, wid = tid >> 5;
    const int g = lane >> 2, c = lane & 3;
    const int iw0 = (wid & 3) * 16;        // warp i-offset
    const int kw0 = (wid >> 2) * 64;       // warp k-offset
    const int i0 = blockIdx.x * 64;
    const int jb = blockIdx.y * 32;
    const float* __restrict__ Hf = d_H + 2 * B_SZ * HID;

    // A (Hf) -> smem packed bf16x2 along h: sApk[h2][i]
    #pragma unroll 4
    for (int t = 0; t < 32; ++t) {
        int idx = tid + t * 256;           // 0..8191
        int ii = idx & 63, h2 = idx >> 6;  // h2 0..127
        float2 v = *(const float2*)(Hf + (i0 + ii) * 256 + 2 * h2);
        sApk[h2 * 72 + ii] = pack_bf2(v.x, v.y);
    }
    // X -> smem [jj][i] fp32
    #pragma unroll
    for (int t = 0; t < 8; ++t) {
        int idx = tid + t * 256;
        int jj = idx & 31, ii = idx >> 5;
        sX[jj * 72 + ii] = d_X[(i0 + ii) * FEAT + jb + jj];
    }

    // B stage loader mapping: r2 = k2 row (and r2+8), c4 = 4 cols
    const int r2 = tid >> 5;
    const int c4 = (tid & 31) * 4;

    // prefetch stage 0 (jj=0, h window 0..31) into buffer 0
    {
        const float* gp = W2 + (size_t)(2 * r2) * W2COLS + (size_t)jb * 128 + c4;
        float4 lo0 = *(const float4*)gp;
        float4 hi0 = *(const float4*)(gp + (size_t)W2COLS);
        float4 lo1 = *(const float4*)(gp + (size_t)16 * W2COLS);
        float4 hi1 = *(const float4*)(gp + (size_t)17 * W2COLS);
        uint4 w0 = make_uint4(pack_bf2(lo0.x, hi0.x), pack_bf2(lo0.y, hi0.y),
                              pack_bf2(lo0.z, hi0.z), pack_bf2(lo0.w, hi0.w));
        uint4 w1 = make_uint4(pack_bf2(lo1.x, hi1.x), pack_bf2(lo1.y, hi1.y),
                              pack_bf2(lo1.z, hi1.z), pack_bf2(lo1.w, hi1.w));
        *(uint4*)&sBpk[r2 * 136 + c4] = w0;
        *(uint4*)&sBpk[(r2 + 8) * 136 + c4] = w1;
    }
    __syncthreads();

    float xacc[8][4] = {};
    float facc[8][4] = {};
    for (int s = 0; s < 256; ++s) {            // 32 j * 8 h-stages(32h each)
        const int buf = s & 1;
        float4 lo0, hi0, lo1, hi1;
        const bool pf = (s + 1 < 256);
        if (pf) {
            int s1 = s + 1;
            int jj2 = s1 >> 3, hb2 = (s1 & 7) * 32;
            const float* gp = W2 + (size_t)(hb2 + 2 * r2) * W2COLS
                                 + (size_t)(jb + jj2) * 128 + c4;
            lo0 = *(const float4*)gp;
            hi0 = *(const float4*)(gp + (size_t)W2COLS);
            lo1 = *(const float4*)(gp + (size_t)16 * W2COLS);
            hi1 = *(const float4*)(gp + (size_t)17 * W2COLS);
        }
        const uint32_t* bbuf = sBpk + buf * 2176;
        const int kb2base = (s & 7) * 16;       // k2 base of this 32-h window
        #pragma unroll
        for (int ks = 0; ks < 2; ++ks) {
            const int kb2 = kb2base + ks * 8;
            uint32_t a0 = sApk[(kb2 + c) * 72 + iw0 + g];
            uint32_t a1 = sApk[(kb2 + c) * 72 + iw0 + g + 8];
            uint32_t a2 = sApk[(kb2 + c + 4) * 72 + iw0 + g];
            uint32_t a3 = sApk[(kb2 + c + 4) * 72 + iw0 + g + 8];
            #pragma unroll
            for (int t = 0; t < 8; ++t) {
                uint32_t b0 = bbuf[(ks * 8 + c) * 136 + kw0 + t * 8 + g];
                uint32_t b1 = bbuf[(ks * 8 + c + 4) * 136 + kw0 + t * 8 + g];
                asm volatile(
                    "mma.sync.aligned.m16n8k16.row.col.f32.bf16.bf16.f32 "
                    "{%0,%1,%2,%3},{%4,%5,%6,%7},{%8,%9},{%0,%1,%2,%3};"
                    : "+f"(facc[t][0]), "+f"(facc[t][1]),
                      "+f"(facc[t][2]), "+f"(facc[t][3])
                    : "r"(a0), "r"(a1), "r"(a2), "r"(a3), "r"(b0), "r"(b1));
            }
        }
        if (pf) {
            uint32_t* dst = sBpk + (buf ^ 1) * 2176;
            uint4 w0 = make_uint4(pack_bf2(lo0.x, hi0.x), pack_bf2(lo0.y, hi0.y),
                                  pack_bf2(lo0.z, hi0.z), pack_bf2(lo0.w, hi0.w));
            uint4 w1 = make_uint4(pack_bf2(lo1.x, hi1.x), pack_bf2(lo1.y, hi1.y),
                                  pack_bf2(lo1.z, hi1.z), pack_bf2(lo1.w, hi1.w));
            *(uint4*)&dst[r2 * 136 + c4] = w0;
            *(uint4*)&dst[(r2 + 8) * 136 + c4] = w1;
        }
        if ((s & 7) == 7) {                    // end of one j: contract with X
            int jj = s >> 3;
            float xv0 = sX[jj * 72 + iw0 + g];
            float xv1 = sX[jj * 72 + iw0 + g + 8];
            #pragma unroll
            for (int t = 0; t < 8; ++t) {
                xacc[t][0] = fmaf(xv0, facc[t][0], xacc[t][0]);
                xacc[t][1] = fmaf(xv0, facc[t][1], xacc[t][1]);
                xacc[t][2] = fmaf(xv1, facc[t][2], xacc[t][2]);
                xacc[t][3] = fmaf(xv1, facc[t][3], xacc[t][3]);
                facc[t][0] = 0.f; facc[t][1] = 0.f;
                facc[t][2] = 0.f; facc[t][3] = 0.f;
            }
        }
        __syncthreads();
    }

    // write partial plane (rows g/g+8, cols 2c/2c+1 per mma C layout)
    float* outp = d_X2p + (size_t)blockIdx.y * (B_SZ * ED) + (size_t)i0 * 128;
    #pragma unroll
    for (int t = 0; t < 8; ++t) {
        int col = kw0 + t * 8 + 2 * c;
        int row0 = iw0 + g, row1 = iw0 + g + 8;
        *(float2*)&outp[row0 * 128 + col] = make_float2(xacc[t][0], xacc[t][1]);
        *(float2*)&outp[row1 * 128 + col] = make_float2(xacc[t][2], xacc[t][3]);
    }
}

__global__ void k_reduce() {
    int idx = blockIdx.x * 256 + threadIdx.x;
    float a = d_fcb[idx];
    #pragma unroll 4
    for (int p = 0; p < NJC; ++p) a += d_X2p[p * (B_SZ * ED) + idx];
    d_X2[idx] = a;
}

__global__ void k_bn2() {
    int k = threadIdx.x;   // 128 threads
    float s = 0.f, ss = 0.f;
    for (int i = 0; i < B_SZ; ++i) {
        float v = d_X2[i * 128 + k]; s += v; ss += v * v;
    }
    const float inv = 1.0f / B_SZ;
    float m = s * inv, var = ss * inv - m * m;
    float istd = rsqrtf(var + 1e-5f);
    for (int i = 0; i < B_SZ; ++i) {
        float v = (d_X2[i * 128 + k] - m) * istd;
        d_Xbn[i * 128 + k] = fmaxf(v, 0.f);
    }
}

__global__ void __launch_bounds__(256) k_final(const float* __restrict__ E2,
                                               const float* __restrict__ bias,
                                               float* __restrict__ out) {
    extern __shared__ float sm[];
    float* sA = sm;                 // [128][132]
    float* sB = sm + 128 * 132;     // [64][132]
    const int tid = threadIdx.x;
    const int ty = tid >> 4, tx = tid & 15;
    const int i0 = blockIdx.y * 128;
    const int n0 = blockIdx.x * 64;
    for (int t = 0; t < 64; ++t) {
        int idx = tid + t * 256;
        int ii = idx >> 7, k = idx & 127;
        sA[ii * 132 + k] = d_Xbn[(i0 + ii) * 128 + k];
    }
    for (int t = 0; t < 32; ++t) {
        int idx = tid + t * 256;
        int nn = idx >> 7, k = idx & 127;
        int n = n0 + nn;
        sB[nn * 132 + k] = (n < NENT) ? E2[(size_t)n * 128 + k] : 0.f;
    }
    __syncthreads();
    float acc[8][4] = {};
    for (int k4 = 0; k4 < 128; k4 += 4) {
        float4 bv[4];
        #pragma unroll
        for (int v = 0; v < 4; ++v)
            bv[v] = *(const float4*)&sB[(tx * 4 + v) * 132 + k4];
        #pragma unroll
        for (int u = 0; u < 8; ++u) {
            float4 a = *(const float4*)&sA[(ty * 8 + u) * 132 + k4];
            #pragma unroll
            for (int v = 0; v < 4; ++v) {
                acc[u][v] = fmaf(a.x, bv[v].x, acc[u][v]);
                acc[u][v] = fmaf(a.y, bv[v].y, acc[u][v]);
                acc[u][v] = fmaf(a.z, bv[v].z, acc[u][v]);
                acc[u][v] = fmaf(a.w, bv[v].w, acc[u][v]);
            }
        }
    }
    #pragma unroll
    for (int v = 0; v < 4; ++v) {
        int n = n0 + tx * 4 + v;
        if (n >= NENT) continue;
        float bb = bias[n];
        #pragma unroll
        for (int u = 0; u < 8; ++u) {
            int i = i0 + ty * 8 + u;
            float logit = acc[u][v] + bb;
            out[(size_t)i * NENT + n] = 1.f / (1.f + __expf(-logit));
        }
    }
}

extern "C" void kernel_launch(void* const* d_in, const int* in_sizes, int n_in,
                              void* d_out, int out_size) {
    const int*   e1       = (const int*)d_in[0];
    const int*   r        = (const int*)d_in[1];
    const float* ent      = (const float*)d_in[2];
    const float* rel      = (const float*)d_in[3];
    const float* convw_w1 = (const float*)d_in[4];
    const float* convw_w2 = (const float*)d_in[5];
    const float* convb_w1 = (const float*)d_in[6];
    const float* convb_w2 = (const float*)d_in[7];
    const float* fcw_w1   = (const float*)d_in[8];
    const float* fcw_w2   = (const float*)d_in[9];
    const float* fcb_w1   = (const float*)d_in[10];
    const float* fcb_w2   = (const float*)d_in[11];
    const float* bias     = (const float*)d_in[12];
    float* out = (float*)d_out;

    cudaFuncSetAttribute(k_bigfused, cudaFuncAttributeMaxDynamicSharedMemorySize, 63488);
    cudaFuncSetAttribute(k_final, cudaFuncAttributeMaxDynamicSharedMemorySize, 101376);

    k_gather<<<128, 256>>>(e1, r, ent, rel);
    k_bn0<<<1, 256>>>();
    k_cpg1<<<dim3(4, 4, 4), 256>>>(convw_w1, convb_w1, fcw_w1, fcb_w1);
    k_cpg2<<<dim3(5, 4, 3), 256>>>(convw_w2, convb_w2, fcb_w2);
    k_conv<<<256, 256>>>();
    k_bigfused<<<dim3(4, NJC), 256, 63488>>>(fcw_w2);
    k_reduce<<<128, 256>>>();
    k_bn2<<<1, 128>>>();
    k_final<<<dim3(640, 2), 256, 101376>>>(ent, bias, out);
}

// round 10
// speedup vs baseline: 3.2730x; 1.2941x over previous
#include <cuda_runtime.h>
#include <cuda_bf16.h>
#include <cstdint>

#define B_SZ 256
#define ED   128
#define HID  256
#define FEAT 2688
#define NENT 40943
#define W2COLS 344064   // FEAT*ED
#define NJC  84         // 84 * 32 = 2688 j-chunks

__device__ float d_E1[B_SZ * ED];
__device__ float d_R[B_SZ * ED];
__device__ float d_stats[2];
__device__ float d_H[4 * B_SZ * HID];      // planes: Hc, Hcb, Hf, Hfb
__device__ float d_filt[B_SZ * 288];
__device__ float d_cbias[B_SZ * 32];
__device__ float d_fcb[B_SZ * ED];
__device__ float d_X[B_SZ * FEAT];
__device__ float d_X2p[NJC * B_SZ * ED];   // split-j partials
__device__ float d_X2[B_SZ * ED];
__device__ float d_Xbn[B_SZ * ED];
// W2 pre-packed to bf16 pairs: P[h2][col] = bf2(W2[2h2][col], W2[2h2+1][col])
__device__ uint32_t d_W2bf[128 * W2COLS];  // 176 MB

__device__ __forceinline__ uint32_t pack_bf2(float lo, float hi) {
    __nv_bfloat162 b = __floats2bfloat162_rn(lo, hi);   // x=lo(low16), y=hi
    return *reinterpret_cast<uint32_t*>(&b);
}
__device__ __forceinline__ uint32_t smem_u32(const void* p) {
    return (uint32_t)__cvta_generic_to_shared(p);
}
#define CP16(d, s) asm volatile("cp.async.cg.shared.global [%0], [%1], 16;" :: "r"(d), "l"(s))
#define CP_COMMIT() asm volatile("cp.async.commit_group;")
#define CP_WAIT2()  asm volatile("cp.async.wait_group 2;")

__global__ void k_gather(const int* __restrict__ e1, const int* __restrict__ r,
                         const float* __restrict__ ent, const float* __restrict__ rel) {
    int idx = blockIdx.x * 256 + threadIdx.x;
    int i = idx >> 7, c = idx & 127;
    d_E1[idx] = ent[(size_t)e1[i] * ED + c];
    d_R[idx]  = rel[(size_t)r[i]  * ED + c];
}

// pack W2 fp32 -> bf16x2 (k-pairs along h) once per launch
__global__ void k_w2cast(const float* __restrict__ W2) {
    int h2 = blockIdx.y;
    int col = blockIdx.x * 1024 + threadIdx.x * 4;
    const float4 lo = *(const float4*)(W2 + (size_t)(2 * h2) * W2COLS + col);
    const float4 hi = *(const float4*)(W2 + (size_t)(2 * h2 + 1) * W2COLS + col);
    uint4 w = make_uint4(pack_bf2(lo.x, hi.x), pack_bf2(lo.y, hi.y),
                         pack_bf2(lo.z, hi.z), pack_bf2(lo.w, hi.w));
    *(uint4*)&d_W2bf[(size_t)h2 * W2COLS + col] = w;
}

__global__ void k_bn0() {
    __shared__ float rs[8], rss[8];
    int tid = threadIdx.x;
    float s = 0.f, ss = 0.f;
    for (int idx = tid; idx < B_SZ * ED; idx += 256) {
        float v = d_E1[idx]; s += v; ss += v * v;
    }
    for (int o = 16; o; o >>= 1) {
        s  += __shfl_xor_sync(0xffffffffu, s,  o);
        ss += __shfl_xor_sync(0xffffffffu, ss, o);
    }
    if ((tid & 31) == 0) { rs[tid >> 5] = s; rss[tid >> 5] = ss; }
    __syncthreads();
    if (tid == 0) {
        float S = 0.f, SS = 0.f;
        for (int w = 0; w < 8; ++w) { S += rs[w]; SS += rss[w]; }
        const float inv = 1.0f / (B_SZ * ED);
        float m = S * inv, var = SS * inv - m * m;
        d_stats[0] = m; d_stats[1] = rsqrtf(var + 1e-5f);
    }
}

__device__ __forceinline__ void gemm64_body(const float* __restrict__ A,
                                            const float* __restrict__ Bw,
                                            float* __restrict__ C,
                                            int K, int N, int doRelu,
                                            int i0, int n0) {
    __shared__ float sA[16 * 64];
    __shared__ float sB[16 * 64];
    const int tid = threadIdx.x;
    const int ty = tid >> 4, tx = tid & 15;
    float acc[4][4] = {};
    for (int kb = 0; kb < K; kb += 16) {
        #pragma unroll
        for (int t = 0; t < 4; ++t) {
            int idx = tid + t * 256;
            int kk = idx & 15, ii = idx >> 4;
            sA[kk * 64 + ii] = A[(i0 + ii) * K + kb + kk];
            int nn = idx & 63, kk2 = idx >> 6;
            int n = n0 + nn;
            sB[kk2 * 64 + nn] = (n < N) ? Bw[(size_t)(kb + kk2) * N + n] : 0.f;
        }
        __syncthreads();
        #pragma unroll
        for (int kk = 0; kk < 16; ++kk) {
            float a[4], b[4];
            #pragma unroll
            for (int u = 0; u < 4; ++u) a[u] = sA[kk * 64 + ty * 4 + u];
            #pragma unroll
            for (int v = 0; v < 4; ++v) b[v] = sB[kk * 64 + tx * 4 + v];
            #pragma unroll
            for (int u = 0; u < 4; ++u)
                #pragma unroll
                for (int v = 0; v < 4; ++v)
                    acc[u][v] = fmaf(a[u], b[v], acc[u][v]);
        }
        __syncthreads();
    }
    #pragma unroll
    for (int u = 0; u < 4; ++u) {
        int row = i0 + ty * 4 + u;
        #pragma unroll
        for (int v = 0; v < 4; ++v) {
            int col = n0 + tx * 4 + v;
            if (col < N) {
                float val = acc[u][v];
                if (doRelu) val = fmaxf(val, 0.f);
                C[(size_t)row * N + col] = val;
            }
        }
    }
}

__global__ void k_cpg1(const float* __restrict__ w0, const float* __restrict__ w1,
                       const float* __restrict__ w2, const float* __restrict__ w3) {
    const float* Bw = (blockIdx.z == 0) ? w0 : (blockIdx.z == 1) ? w1
                    : (blockIdx.z == 2) ? w2 : w3;
    float* C = d_H + (size_t)blockIdx.z * (B_SZ * HID);
    gemm64_body(d_R, Bw, C, 128, 256, 1, blockIdx.y * 64, blockIdx.x * 64);
}

__global__ void k_cpg2(const float* __restrict__ convw_w2,
                       const float* __restrict__ convb_w2,
                       const float* __restrict__ fcb_w2) {
    int z = blockIdx.z;
    const float* A;
    const float* Bw;
    float* C;
    int N;
    if (z == 0)      { A = d_H;                  Bw = convw_w2; C = d_filt;  N = 288; }
    else if (z == 1) { A = d_H + B_SZ * HID;     Bw = convb_w2; C = d_cbias; N = 32;  }
    else             { A = d_H + 3 * B_SZ * HID; Bw = fcb_w2;   C = d_fcb;   N = 128; }
    int n0 = blockIdx.x * 64;
    if (n0 >= N) return;
    gemm64_body(A, Bw, C, 256, N, 0, blockIdx.y * 64, n0);
}

__global__ void k_conv() {
    __shared__ float sx[128];
    __shared__ float sf[288];
    __shared__ float scb[32];
    const int i = blockIdx.x, tid = threadIdx.x;
    const float mean = d_stats[0], istd = d_stats[1];
    if (tid < 128) sx[tid] = (d_E1[i * 128 + tid] - mean) * istd;
    if (tid < 32)  scb[tid] = d_cbias[i * 32 + tid];
    for (int q = tid; q < 288; q += 256) sf[q] = d_filt[i * 288 + q];
    __syncthreads();
    for (int oi = tid; oi < FEAT; oi += 256) {
        int c = oi / 84, rem = oi - c * 84;
        int y = rem / 14, x = rem - y * 14;
        float a = scb[c];
        #pragma unroll
        for (int ky = 0; ky < 3; ++ky)
            #pragma unroll
            for (int kx = 0; kx < 3; ++kx)
                a = fmaf(sx[(y + ky) * 16 + (x + kx)], sf[c * 9 + ky * 3 + kx], a);
        d_X[i * FEAT + oi] = fmaxf(a, 0.f);
    }
}

// ---------- dominant contraction: bf16 mma m16n8k16, cp.async 4-stage ring ------
// Block: 64 i-rows x 128 k-cols x 32 j's. Stage = 32 h (16 k2-rows), 256 stages.
__global__ void __launch_bounds__(256, 2) k_bigfused() {
    extern __shared__ uint32_t smw[];
    uint32_t* sApk = smw;                   // 9216 words: [h2=128][72]
    uint32_t* sBpk = smw + 9216;            // 4 stages x 2176 words ([k2=16][136])
    float*    sX   = (float*)(smw + 9216 + 4 * 2176);  // [jj=32][72]
    const int tid = threadIdx.x;
    const int lane = tid & 31, wid = tid >> 5;
    const int g = lane >> 2, c = lane & 3;
    const int iw0 = (wid & 3) * 16;
    const int kw0 = (wid >> 2) * 64;
    const int i0 = blockIdx.x * 64;
    const int jb = blockIdx.y * 32;
    const float* __restrict__ Hf = d_H + 2 * B_SZ * HID;

    // A (Hf) -> smem packed bf16x2 along h
    #pragma unroll 4
    for (int t = 0; t < 32; ++t) {
        int idx = tid + t * 256;
        int ii = idx & 63, h2 = idx >> 6;
        float2 v = *(const float2*)(Hf + (i0 + ii) * 256 + 2 * h2);
        sApk[h2 * 72 + ii] = pack_bf2(v.x, v.y);
    }
    #pragma unroll
    for (int t = 0; t < 8; ++t) {
        int idx = tid + t * 256;
        int jj = idx & 31, ii = idx >> 5;
        sX[jj * 72 + ii] = d_X[(i0 + ii) * FEAT + jb + jj];
    }

    const int r2 = tid >> 5;            // k2 row 0..7 (and +8)
    const int c4 = (tid & 31) * 4;      // col group

    // stage s: jj = s>>3, h-window = s&7 (16 k2 rows each)
    #pragma unroll 1
    for (int p = 0; p < 3; ++p) {
        int jj = p >> 3, hw = p & 7;
        const uint32_t* gp = d_W2bf + (size_t)(hw * 16 + r2) * W2COLS
                                    + (size_t)(jb + jj) * 128 + c4;
        uint32_t* dp = sBpk + (p & 3) * 2176 + r2 * 136 + c4;
        CP16(smem_u32(dp), gp);
        CP16(smem_u32(dp + 8 * 136), gp + (size_t)8 * W2COLS);
        CP_COMMIT();
    }

    float xacc[8][4] = {};
    float facc[8][4] = {};
    for (int s = 0; s < 256; ++s) {
        CP_WAIT2();
        __syncthreads();
        const uint32_t* bbuf = sBpk + (s & 3) * 2176;
        const int kb2base = (s & 7) * 16;
        #pragma unroll
        for (int ks = 0; ks < 2; ++ks) {
            const int kb2 = kb2base + ks * 8;
            uint32_t a0 = sApk[(kb2 + c) * 72 + iw0 + g];
            uint32_t a1 = sApk[(kb2 + c) * 72 + iw0 + g + 8];
            uint32_t a2 = sApk[(kb2 + c + 4) * 72 + iw0 + g];
            uint32_t a3 = sApk[(kb2 + c + 4) * 72 + iw0 + g + 8];
            #pragma unroll
            for (int t = 0; t < 8; ++t) {
                uint32_t b0 = bbuf[(ks * 8 + c) * 136 + kw0 + t * 8 + g];
                uint32_t b1 = bbuf[(ks * 8 + c + 4) * 136 + kw0 + t * 8 + g];
                asm volatile(
                    "mma.sync.aligned.m16n8k16.row.col.f32.bf16.bf16.f32 "
                    "{%0,%1,%2,%3},{%4,%5,%6,%7},{%8,%9},{%0,%1,%2,%3};"
                    : "+f"(facc[t][0]), "+f"(facc[t][1]),
                      "+f"(facc[t][2]), "+f"(facc[t][3])
                    : "r"(a0), "r"(a1), "r"(a2), "r"(a3), "r"(b0), "r"(b1));
            }
        }
        if (s + 3 < 256) {
            int s3 = s + 3;
            int jj = s3 >> 3, hw = s3 & 7;
            const uint32_t* gp = d_W2bf + (size_t)(hw * 16 + r2) * W2COLS
                                        + (size_t)(jb + jj) * 128 + c4;
            uint32_t* dp = sBpk + (s3 & 3) * 2176 + r2 * 136 + c4;
            CP16(smem_u32(dp), gp);
            CP16(smem_u32(dp + 8 * 136), gp + (size_t)8 * W2COLS);
        }
        CP_COMMIT();
        if ((s & 7) == 7) {                 // end of one j: contract with X
            int jj = s >> 3;
            float xv0 = sX[jj * 72 + iw0 + g];
            float xv1 = sX[jj * 72 + iw0 + g + 8];
            #pragma unroll
            for (int t = 0; t < 8; ++t) {
                xacc[t][0] = fmaf(xv0, facc[t][0], xacc[t][0]);
                xacc[t][1] = fmaf(xv0, facc[t][1], xacc[t][1]);
                xacc[t][2] = fmaf(xv1, facc[t][2], xacc[t][2]);
                xacc[t][3] = fmaf(xv1, facc[t][3], xacc[t][3]);
                facc[t][0] = 0.f; facc[t][1] = 0.f;
                facc[t][2] = 0.f; facc[t][3] = 0.f;
            }
        }
    }

    float* outp = d_X2p + (size_t)blockIdx.y * (B_SZ * ED) + (size_t)i0 * 128;
    #pragma unroll
    for (int t = 0; t < 8; ++t) {
        int col = kw0 + t * 8 + 2 * c;
        int row0 = iw0 + g, row1 = iw0 + g + 8;
        *(float2*)&outp[row0 * 128 + col] = make_float2(xacc[t][0], xacc[t][1]);
        *(float2*)&outp[row1 * 128 + col] = make_float2(xacc[t][2], xacc[t][3]);
    }
}

__global__ void k_reduce() {
    int idx = blockIdx.x * 256 + threadIdx.x;
    float a = d_fcb[idx];
    #pragma unroll 4
    for (int p = 0; p < NJC; ++p) a += d_X2p[p * (B_SZ * ED) + idx];
    d_X2[idx] = a;
}

__global__ void k_bn2() {
    int k = threadIdx.x;
    float s = 0.f, ss = 0.f;
    for (int i = 0; i < B_SZ; ++i) {
        float v = d_X2[i * 128 + k]; s += v; ss += v * v;
    }
    const float inv = 1.0f / B_SZ;
    float m = s * inv, var = ss * inv - m * m;
    float istd = rsqrtf(var + 1e-5f);
    for (int i = 0; i < B_SZ; ++i) {
        float v = (d_X2[i * 128 + k] - m) * istd;
        d_Xbn[i * 128 + k] = fmaxf(v, 0.f);
    }
}

__global__ void __launch_bounds__(256) k_final(const float* __restrict__ E2,
                                               const float* __restrict__ bias,
                                               float* __restrict__ out) {
    extern __shared__ float sm[];
    float* sA = sm;                 // [128][132]
    float* sB = sm + 128 * 132;     // [64][132]
    const int tid = threadIdx.x;
    const int ty = tid >> 4, tx = tid & 15;
    const int i0 = blockIdx.y * 128;
    const int n0 = blockIdx.x * 64;
    for (int t = 0; t < 64; ++t) {
        int idx = tid + t * 256;
        int ii = idx >> 7, k = idx & 127;
        sA[ii * 132 + k] = d_Xbn[(i0 + ii) * 128 + k];
    }
    for (int t = 0; t < 32; ++t) {
        int idx = tid + t * 256;
        int nn = idx >> 7, k = idx & 127;
        int n = n0 + nn;
        sB[nn * 132 + k] = (n < NENT) ? E2[(size_t)n * 128 + k] : 0.f;
    }
    __syncthreads();
    float acc[8][4] = {};
    for (int k4 = 0; k4 < 128; k4 += 4) {
        float4 bv[4];
        #pragma unroll
        for (int v = 0; v < 4; ++v)
            bv[v] = *(const float4*)&sB[(tx * 4 + v) * 132 + k4];
        #pragma unroll
        for (int u = 0; u < 8; ++u) {
            float4 a = *(const float4*)&sA[(ty * 8 + u) * 132 + k4];
            #pragma unroll
            for (int v = 0; v < 4; ++v) {
                acc[u][v] = fmaf(a.x, bv[v].x, acc[u][v]);
                acc[u][v] = fmaf(a.y, bv[v].y, acc[u][v]);
                acc[u][v] = fmaf(a.z, bv[v].z, acc[u][v]);
                acc[u][v] = fmaf(a.w, bv[v].w, acc[u][v]);
            }
        }
    }
    #pragma unroll
    for (int v = 0; v < 4; ++v) {
        int n = n0 + tx * 4 + v;
        if (n >= NENT) continue;
        float bb = bias[n];
        #pragma unroll
        for (int u = 0; u < 8; ++u) {
            int i = i0 + ty * 8 + u;
            float logit = acc[u][v] + bb;
            out[(size_t)i * NENT + n] = 1.f / (1.f + __expf(-logit));
        }
    }
}

extern "C" void kernel_launch(void* const* d_in, const int* in_sizes, int n_in,
                              void* d_out, int out_size) {
    const int*   e1       = (const int*)d_in[0];
    const int*   r        = (const int*)d_in[1];
    const float* ent      = (const float*)d_in[2];
    const float* rel      = (const float*)d_in[3];
    const float* convw_w1 = (const float*)d_in[4];
    const float* convw_w2 = (const float*)d_in[5];
    const float* convb_w1 = (const float*)d_in[6];
    const float* convb_w2 = (const float*)d_in[7];
    const float* fcw_w1   = (const float*)d_in[8];
    const float* fcw_w2   = (const float*)d_in[9];
    const float* fcb_w1   = (const float*)d_in[10];
    const float* fcb_w2   = (const float*)d_in[11];
    const float* bias     = (const float*)d_in[12];
    float* out = (float*)d_out;

    cudaFuncSetAttribute(k_bigfused, cudaFuncAttributeMaxDynamicSharedMemorySize, 80896);
    cudaFuncSetAttribute(k_final, cudaFuncAttributeMaxDynamicSharedMemorySize, 101376);

    k_w2cast<<<dim3(336, 128), 256>>>(fcw_w2);
    k_gather<<<128, 256>>>(e1, r, ent, rel);
    k_bn0<<<1, 256>>>();
    k_cpg1<<<dim3(4, 4, 4), 256>>>(convw_w1, convb_w1, fcw_w1, fcb_w1);
    k_cpg2<<<dim3(5, 4, 3), 256>>>(convw_w2, convb_w2, fcb_w2);
    k_conv<<<256, 256>>>();
    k_bigfused<<<dim3(4, NJC), 256, 80896>>>();
    k_reduce<<<128, 256>>>();
    k_bn2<<<1, 128>>>();
    k_final<<<dim3(640, 2), 256, 101376>>>(ent, bias, out);
}